// round 2
// baseline (speedup 1.0000x reference)
#include <cuda_runtime.h>

#define BB   32
#define SS   1024
#define DD   512
#define D2   1024
#define D3   1536
#define VV   49000
#define VP   49152
#define VF   50000
#define NCB  24

__device__ __align__(16) float g_decop_t[D2 * BB];
__device__ __align__(16) float g_temp_t [D3 * BB];
__device__ __align__(16) float g_dec1   [BB * D2];
__device__ __align__(16) float g_scores [BB * SS];
__device__ __align__(16) float g_attn   [BB * SS];
__device__ __align__(16) float g_ctxpart[8 * BB * D2];
__device__ __align__(16) float g_hidden [BB * DD];
__device__            float g_pgen  [BB];
__device__            float g_scale [BB];
__device__ __align__(16) float g_lpart [2 * BB * VP];
__device__            float g_esum  [BB * NCB];

__device__ __forceinline__ float fast_tanh(float x) {
    float y;
    asm("tanh.approx.f32 %0, %1;" : "=f"(y) : "f"(x));
    return y;
}

// K0: transpose stage: g_decop_t[k][b] = [h;c], g_temp_t rows 0..511 = dec_output
__global__ void k0_stage(const float* __restrict__ h, const float* __restrict__ c,
                         const float* __restrict__ dec_output) {
    int i = blockIdx.x * 256 + threadIdx.x;   // 0..32767
    int k = i >> 5, b = i & 31;
    float x = (k < DD) ? h[b * DD + k] : c[b * DD + (k - DD)];
    g_decop_t[i] = x;
    if (k < DD) g_temp_t[i] = dec_output[b * DD + k];
}

// K1: dec_op1 = dec_op @ W_dec^T + b_dec
__global__ void k1_dec1(const float* __restrict__ W, const float* __restrict__ bias) {
    int t = threadIdx.x;
    int b = t & 31, g = t >> 5;
    int j0 = blockIdx.x * 8;
    float acc[8];
#pragma unroll
    for (int jj = 0; jj < 8; jj++) acc[jj] = 0.f;
    int k0 = g * 128;
    for (int k = k0; k < k0 + 128; k++) {
        float x = g_decop_t[k * 32 + b];
#pragma unroll
        for (int jj = 0; jj < 8; jj++)
            acc[jj] += W[(j0 + jj) * D2 + k] * x;
    }
    __shared__ float sred[8][8][32];
#pragma unroll
    for (int jj = 0; jj < 8; jj++) sred[g][jj][b] = acc[jj];
    __syncthreads();
    int jj = t >> 5, bo = t & 31;
    float tot = bias[j0 + jj];
#pragma unroll
    for (int gg = 0; gg < 8; gg++) tot += sred[gg][jj][bo];
    g_dec1[bo * D2 + j0 + jj] = tot;
}

// K2: scores[b,s] = sum_d tanh(enc_op1+dec_op1)*w_attn — warp per (b,s) row
__global__ void k2_scores(const float4* __restrict__ enc1,
                          const float4* __restrict__ wattn) {
    int t = threadIdx.x;
    int lane = t & 31, w = t >> 5;
    int row = blockIdx.x * 8 + w;             // b*1024 + s
    int b = row >> 10;
    const float4* d1 = ((const float4*)g_dec1) + b * 256;
    float acc = 0.f;
#pragma unroll
    for (int i = 0; i < 8; i++) {
        int c = i * 32 + lane;
        float4 e  = enc1[(size_t)row * 256 + c];
        float4 dd = d1[c];
        float4 wa = wattn[c];
        acc += fast_tanh(e.x + dd.x) * wa.x;
        acc += fast_tanh(e.y + dd.y) * wa.y;
        acc += fast_tanh(e.z + dd.z) * wa.z;
        acc += fast_tanh(e.w + dd.w) * wa.w;
    }
#pragma unroll
    for (int o = 16; o; o >>= 1) acc += __shfl_down_sync(0xffffffffu, acc, o);
    if (!lane) g_scores[row] = acc;
}

// K3: masked softmax + renorm; write attn scratch + d_out
__global__ void k3_softmax(const int* __restrict__ src, float* __restrict__ out_attn) {
    int b = blockIdx.x, t = threadIdx.x;
    __shared__ float sm[8];
    __shared__ float bc;
    float4 s = ((const float4*)g_scores)[b * 256 + t];
    float m = fmaxf(fmaxf(s.x, s.y), fmaxf(s.z, s.w));
#pragma unroll
    for (int o = 16; o; o >>= 1) m = fmaxf(m, __shfl_down_sync(0xffffffffu, m, o));
    if (!(t & 31)) sm[t >> 5] = m;
    __syncthreads();
    if (t == 0) {
        float mm = sm[0];
#pragma unroll
        for (int i = 1; i < 8; i++) mm = fmaxf(mm, sm[i]);
        bc = mm;
    }
    __syncthreads();
    float mx = bc;
    __syncthreads();
    int4 id = ((const int4*)src)[b * 256 + t];
    float4 e;
    e.x = (id.x != 0) ? __expf(s.x - mx) : 0.f;
    e.y = (id.y != 0) ? __expf(s.y - mx) : 0.f;
    e.z = (id.z != 0) ? __expf(s.z - mx) : 0.f;
    e.w = (id.w != 0) ? __expf(s.w - mx) : 0.f;
    float sum = e.x + e.y + e.z + e.w;
#pragma unroll
    for (int o = 16; o; o >>= 1) sum += __shfl_down_sync(0xffffffffu, sum, o);
    if (!(t & 31)) sm[t >> 5] = sum;
    __syncthreads();
    if (t == 0) {
        float tt = 0.f;
#pragma unroll
        for (int i = 0; i < 8; i++) tt += sm[i];
        bc = 1.f / tt;
    }
    __syncthreads();
    float inv = bc;
    float4 a = make_float4(e.x * inv, e.y * inv, e.z * inv, e.w * inv);
    ((float4*)g_attn)[b * 256 + t] = a;
    ((float4*)out_attn)[b * 256 + t] = a;
}

// K4: context partials over S chunks of 128
__global__ void k4_ctx(const float4* __restrict__ enc) {
    int sc = blockIdx.x, b = blockIdx.y, t = threadIdx.x;
    float4 acc = make_float4(0.f, 0.f, 0.f, 0.f);
    int s0 = sc * 128;
    const float*  at   = g_attn + b * SS + s0;
    const float4* base = enc + (size_t)(b * SS + s0) * 256 + t;
#pragma unroll 4
    for (int s = 0; s < 128; s++) {
        float  a = at[s];
        float4 e = base[(size_t)s * 256];
        acc.x += a * e.x; acc.y += a * e.y; acc.z += a * e.z; acc.w += a * e.w;
    }
    ((float4*)g_ctxpart)[(sc * 32 + b) * 256 + t] = acc;
}

// K5: reduce + BN; write ctx (temp_t rows 512.. + d_out); fused p_gen
__global__ void k5_bn_pgen(const float* __restrict__ bn_m, const float* __restrict__ bn_v,
                           const float* __restrict__ gam,  const float* __restrict__ bet,
                           const float* __restrict__ Wp,   const float* __restrict__ bp,
                           const float* __restrict__ hh,   const float* __restrict__ cc,
                           const float* __restrict__ dinp, float* __restrict__ out_ctx) {
    int b = blockIdx.x, t = threadIdx.x;
    float sv[4] = {0.f, 0.f, 0.f, 0.f};
#pragma unroll
    for (int sc = 0; sc < 8; sc++) {
        float4 p = ((const float4*)g_ctxpart)[(sc * 32 + b) * 256 + t];
        sv[0] += p.x; sv[1] += p.y; sv[2] += p.z; sv[3] += p.w;
    }
    int d = 4 * t;
    float ctx[4];
    float pp = 0.f;
#pragma unroll
    for (int i = 0; i < 4; i++) {
        int dd = d + i;
        float cx = (sv[i] - bn_m[dd]) * rsqrtf(bn_v[dd] + 1e-5f) * gam[dd] + bet[dd];
        ctx[i] = cx;
        g_temp_t[(DD + dd) * 32 + b] = cx;
        float dop = (dd < DD) ? hh[b * DD + dd] : cc[b * DD + dd - DD];
        pp += Wp[dd] * cx + Wp[D2 + dd] * dop;
    }
    ((float4*)out_ctx)[b * 256 + t] = make_float4(ctx[0], ctx[1], ctx[2], ctx[3]);
    if (t < 128) {
#pragma unroll
        for (int i = 0; i < 4; i++) {
            int dd = 4 * t + i;
            pp += Wp[2048 + dd] * dinp[b * DD + dd];
        }
    }
    __shared__ float sm[8];
#pragma unroll
    for (int o = 16; o; o >>= 1) pp += __shfl_down_sync(0xffffffffu, pp, o);
    if (!(t & 31)) sm[t >> 5] = pp;
    __syncthreads();
    if (t == 0) {
        float tot = bp[0];
#pragma unroll
        for (int i = 0; i < 8; i++) tot += sm[i];
        g_pgen[b] = 1.f / (1.f + __expf(-tot));
    }
}

// K6: hidden = temp @ W_v1^T + b_v1
__global__ void k6_hidden(const float* __restrict__ W, const float* __restrict__ bias) {
    int t = threadIdx.x;
    int b = t & 31, g = t >> 5;
    int j0 = blockIdx.x * 8;
    float acc[8];
#pragma unroll
    for (int jj = 0; jj < 8; jj++) acc[jj] = 0.f;
    int k0 = g * 192;
    for (int k = k0; k < k0 + 192; k++) {
        float x = g_temp_t[k * 32 + b];
#pragma unroll
        for (int jj = 0; jj < 8; jj++)
            acc[jj] += W[(j0 + jj) * D3 + k] * x;
    }
    __shared__ float sred[8][8][32];
#pragma unroll
    for (int jj = 0; jj < 8; jj++) sred[g][jj][b] = acc[jj];
    __syncthreads();
    int jj = t >> 5, bo = t & 31;
    float tot = bias[j0 + jj];
#pragma unroll
    for (int gg = 0; gg < 8; gg++) tot += sred[gg][jj][bo];
    g_hidden[bo * DD + j0 + jj] = tot;
}

// K8a: vocab GEMM partials, split-K 2. Block 256v x 32b x 256k; thread 4v x 8b.
#define WSTR 20
__global__ __launch_bounds__(256) void k8a_logits(const float* __restrict__ Wv2) {
    __shared__ float Ws[256 * WSTR];
    __shared__ float Hs[32 * 16];
    int t  = threadIdx.x;
    int tv = t & 63, tb = t >> 6;
    int v0 = blockIdx.x * 256;
    int ks = blockIdx.y;
    int kbase = ks * 256;

    float acc[4][8];
#pragma unroll
    for (int j = 0; j < 4; j++)
#pragma unroll
        for (int bj = 0; bj < 8; bj++) acc[j][bj] = 0.f;

    float4 wreg[4];
    float  hreg0, hreg1;
    {
        int k0 = kbase;
#pragma unroll
        for (int li = 0; li < 4; li++) {
            int flat = li * 256 + t;
            int v = flat >> 2, kq = flat & 3;
            int gv = v0 + v;
            wreg[li] = (gv < VV)
                ? *(const float4*)(Wv2 + (size_t)gv * DD + k0 + kq * 4)
                : make_float4(0.f, 0.f, 0.f, 0.f);
        }
        hreg0 = g_hidden[((t)       >> 4) * DD + k0 + ((t)       & 15)];
        hreg1 = g_hidden[((t + 256) >> 4) * DD + k0 + ((t + 256) & 15)];
    }
    {
#pragma unroll
        for (int li = 0; li < 4; li++) {
            int flat = li * 256 + t;
            int v = flat >> 2, kq = flat & 3;
            *(float4*)(Ws + v * WSTR + kq * 4) = wreg[li];
        }
        Hs[t] = hreg0;
        Hs[t + 256] = hreg1;
    }
    __syncthreads();

    for (int tile = 0; tile < 16; tile++) {
        if (tile < 15) {
            int k0 = kbase + (tile + 1) * 16;
#pragma unroll
            for (int li = 0; li < 4; li++) {
                int flat = li * 256 + t;
                int v = flat >> 2, kq = flat & 3;
                int gv = v0 + v;
                wreg[li] = (gv < VV)
                    ? *(const float4*)(Wv2 + (size_t)gv * DD + k0 + kq * 4)
                    : make_float4(0.f, 0.f, 0.f, 0.f);
            }
            hreg0 = g_hidden[((t)       >> 4) * DD + k0 + ((t)       & 15)];
            hreg1 = g_hidden[((t + 256) >> 4) * DD + k0 + ((t + 256) & 15)];
        }
#pragma unroll
        for (int kq = 0; kq < 4; kq++) {
            float4 h[8];
#pragma unroll
            for (int bj = 0; bj < 8; bj++)
                h[bj] = *(const float4*)(Hs + (tb * 8 + bj) * 16 + kq * 4);
#pragma unroll
            for (int j = 0; j < 4; j++) {
                float4 w = *(const float4*)(Ws + (tv + 64 * j) * WSTR + kq * 4);
#pragma unroll
                for (int bj = 0; bj < 8; bj++) {
                    acc[j][bj] += w.x * h[bj].x;
                    acc[j][bj] += w.y * h[bj].y;
                    acc[j][bj] += w.z * h[bj].z;
                    acc[j][bj] += w.w * h[bj].w;
                }
            }
        }
        if (tile < 15) {
            __syncthreads();
#pragma unroll
            for (int li = 0; li < 4; li++) {
                int flat = li * 256 + t;
                int v = flat >> 2, kq = flat & 3;
                *(float4*)(Ws + v * WSTR + kq * 4) = wreg[li];
            }
            Hs[t] = hreg0;
            Hs[t + 256] = hreg1;
            __syncthreads();
        }
    }
#pragma unroll
    for (int j = 0; j < 4; j++) {
        int v = v0 + tv + 64 * j;
#pragma unroll
        for (int bj = 0; bj < 8; bj++) {
            int b = tb * 8 + bj;
            g_lpart[(ks * 32 + b) * VP + v] = acc[j][bj];
        }
    }
}

// K8b: combine split-K + bias, exp, per-(b,chunk) sums
__global__ void k8b_exp(const float* __restrict__ bv2, float* __restrict__ dout) {
    int b = blockIdx.x, cb = blockIdx.y, t = threadIdx.x;
    int base = cb * 2048;
    float sum = 0.f;
#pragma unroll
    for (int it = 0; it < 8; it++) {
        int v = base + it * 256 + t;
        if (v < VV) {
            float l = g_lpart[b * VP + v] + g_lpart[(32 + b) * VP + v] + bv2[v];
            float e = __expf(l);
            dout[(size_t)b * VF + v] = e;
            sum += e;
        }
    }
    __shared__ float sm[8];
#pragma unroll
    for (int o = 16; o; o >>= 1) sum += __shfl_down_sync(0xffffffffu, sum, o);
    if (!(t & 31)) sm[t >> 5] = sum;
    __syncthreads();
    if (t == 0) {
        float tot = 0.f;
#pragma unroll
        for (int i = 0; i < 8; i++) tot += sm[i];
        g_esum[b * NCB + cb] = tot;
    }
}

// K9: scale = p_gen / sum_exp
__global__ void k9_scale() {
    int b = threadIdx.x;
    if (b < 32) {
        float s = 0.f;
#pragma unroll
        for (int i = 0; i < NCB; i++) s += g_esum[b * NCB + i];
        g_scale[b] = g_pgen[b] / s;
    }
}

// K10: p_final = p_gen * softmax; OOV region -> 0
__global__ void k10_finalize(float* __restrict__ dout) {
    int i = blockIdx.x * 256 + threadIdx.x;   // 0..1,599,999
    int b = i / VF;
    int v = i - b * VF;
    float p = (v < VV) ? dout[i] * g_scale[b] : 0.f;
    dout[i] = p;
}

// K11: scatter-add (1-p_gen)*attn
__global__ void k11_scatter(const int* __restrict__ src, float* __restrict__ dout) {
    int b = blockIdx.x, t = threadIdx.x;
    float omp = 1.f - g_pgen[b];
#pragma unroll
    for (int it = 0; it < 4; it++) {
        int s = it * 256 + t;
        int idx = src[b * SS + s];
        float val = omp * g_attn[b * SS + s];
        atomicAdd(dout + (size_t)b * VF + idx, val);
    }
}

// K12: zero-fix — only OOV region can still be exactly 0
__global__ void k12_fix(float* __restrict__ dout) {
    int i = blockIdx.x * 256 + threadIdx.x;   // 0..31999
    int b = i / 1000;
    int v = VV + (i - b * 1000);
    size_t j = (size_t)b * VF + v;
    if (dout[j] == 0.f) dout[j] = 1e-12f;
}

extern "C" void kernel_launch(void* const* d_in, const int* in_sizes, int n_in,
                              void* d_out, int out_size) {
    const float* dec_output = (const float*)d_in[0];
    const float* hh         = (const float*)d_in[1];
    const float* cc         = (const float*)d_in[2];
    const float* dinp       = (const float*)d_in[3];
    const float* enc        = (const float*)d_in[4];
    const float* enc1       = (const float*)d_in[5];
    const int*   src        = (const int*)  d_in[6];
    const float* W_dec      = (const float*)d_in[7];
    const float* b_dec      = (const float*)d_in[8];
    const float* w_attn     = (const float*)d_in[9];
    const float* W_v1       = (const float*)d_in[10];
    const float* b_v1       = (const float*)d_in[11];
    const float* W_v2       = (const float*)d_in[12];
    const float* b_v2       = (const float*)d_in[13];
    const float* W_p        = (const float*)d_in[14];
    const float* b_p        = (const float*)d_in[15];
    const float* gam        = (const float*)d_in[16];
    const float* bet        = (const float*)d_in[17];
    const float* bn_m       = (const float*)d_in[18];
    const float* bn_v       = (const float*)d_in[19];

    float* dout     = (float*)d_out;
    float* out_attn = dout + BB * VF;       // tuple order: p_final, attn, context
    float* out_ctx  = out_attn + BB * SS;

    k0_stage   <<<128, 256>>>(hh, cc, dec_output);
    k1_dec1    <<<128, 256>>>(W_dec, b_dec);
    k2_scores  <<<4096, 256>>>((const float4*)enc1, (const float4*)w_attn);
    k3_softmax <<<32, 256>>>(src, out_attn);
    k4_ctx     <<<dim3(8, 32), 256>>>((const float4*)enc);
    k5_bn_pgen <<<32, 256>>>(bn_m, bn_v, gam, bet, W_p, b_p, hh, cc, dinp, out_ctx);
    k6_hidden  <<<64, 256>>>(W_v1, b_v1);
    k8a_logits <<<dim3(192, 2), 256>>>(W_v2);
    k8b_exp    <<<dim3(32, NCB), 256>>>(b_v2, dout);
    k9_scale   <<<1, 32>>>();
    k10_finalize<<<6250, 256>>>(dout);
    k11_scatter<<<32, 256>>>(src, dout);
    k12_fix    <<<125, 256>>>(dout);
}